// round 1
// baseline (speedup 1.0000x reference)
#include <cuda_runtime.h>
#include <math.h>

// Problem dims
#define BB      8
#define SS      512
#define DDIM    1024
#define HDIM    4096
#define NHEADS  16
#define DHEAD   64
#define MROWS   (BB*SS)        // 4096
#define LN_EPS  1e-5f

// GEMM tiling
#define BM 128
#define BN 64
#define BK 16
#define TM 8
#define TN 4
#define NTHR 256

// ---------------- scratch (device globals; no allocation) ----------------
__device__ float2 g_Q [MROWS*DDIM];
__device__ float2 g_K [MROWS*DDIM];
__device__ float2 g_V [MROWS*DDIM];
__device__ float2 g_O [MROWS*DDIM];
__device__ float2 g_X2[MROWS*DDIM];
__device__ float2 g_Mp[MROWS*DDIM];
__device__ float2 g_Hm[MROWS*HDIM];
__device__ float2 g_Sc[(size_t)BB*NHEADS*SS*SS];

// ---------------- complex GEMM ----------------
// C[m,n] = sum_k A[m,k] * B'[k,n]   (complex product, no conjugate)
// TRANSB=true : B' = B^T with B stored [N,K] row-major (K contiguous)  -> X @ W^T
// TRANSB=false: B' = B   with B stored [K,N] row-major (N contiguous)  -> A @ V
// Batched via blockIdx.z: base offset = (z/zdiv)*s?1 + (z%zdiv)*s?2 for A,B,C.
template<bool TRANSB>
__global__ __launch_bounds__(NTHR)
void cgemm(const float2* __restrict__ A, int lda,
           const float2* __restrict__ B, int ldb,
           float2* __restrict__ C, int ldc,
           int Kdim,
           long sA1, long sA2, long sB1, long sB2, long sC1, long sC2, int zdiv,
           const float2* __restrict__ bias, float scale, int act)
{
    __shared__ float2 As[BK][BM + 2];
    __shared__ float2 Bs[BK][BN + 2];

    const int tid = threadIdx.x;
    const int tx  = tid & 15;   // n group (16 groups of TN=4)
    const int ty  = tid >> 4;   // m group (16 groups of TM=8)

    const int z = blockIdx.z;
    const long offA = (long)(z / zdiv) * sA1 + (long)(z % zdiv) * sA2;
    const long offB = (long)(z / zdiv) * sB1 + (long)(z % zdiv) * sB2;
    const long offC = (long)(z / zdiv) * sC1 + (long)(z % zdiv) * sC2;

    const float2* Ab = A + offA + (long)blockIdx.y * BM * lda;
    const float2* Bb;
    if (TRANSB) Bb = B + offB + (long)blockIdx.x * BN * ldb;
    else        Bb = B + offB + blockIdx.x * BN;

    float accr[TM][TN], acci[TM][TN];
    #pragma unroll
    for (int i = 0; i < TM; i++)
        #pragma unroll
        for (int j = 0; j < TN; j++) { accr[i][j] = 0.f; acci[i][j] = 0.f; }

    for (int k0 = 0; k0 < Kdim; k0 += BK) {
        // load A tile [BM x BK], store transposed As[k][m]
        #pragma unroll
        for (int t = 0; t < (BM*BK)/NTHR; t++) {
            int idx = tid + t*NTHR;
            int m = idx >> 4, k = idx & 15;
            As[k][m] = Ab[(long)m * lda + k0 + k];
        }
        if (TRANSB) {
            #pragma unroll
            for (int t = 0; t < (BN*BK)/NTHR; t++) {
                int idx = tid + t*NTHR;
                int n = idx >> 4, k = idx & 15;
                Bs[k][n] = Bb[(long)n * ldb + k0 + k];
            }
        } else {
            #pragma unroll
            for (int t = 0; t < (BN*BK)/NTHR; t++) {
                int idx = tid + t*NTHR;
                int k = idx / BN, n = idx % BN;
                Bs[k][n] = Bb[(long)(k0 + k) * ldb + n];
            }
        }
        __syncthreads();

        #pragma unroll
        for (int k = 0; k < BK; k++) {
            float2 a[TM], b[TN];
            #pragma unroll
            for (int i = 0; i < TM; i++) a[i] = As[k][ty*TM + i];
            #pragma unroll
            for (int j = 0; j < TN; j++) b[j] = Bs[k][tx*TN + j];
            #pragma unroll
            for (int i = 0; i < TM; i++)
                #pragma unroll
                for (int j = 0; j < TN; j++) {
                    accr[i][j] = fmaf(a[i].x,  b[j].x, accr[i][j]);
                    accr[i][j] = fmaf(-a[i].y, b[j].y, accr[i][j]);
                    acci[i][j] = fmaf(a[i].x,  b[j].y, acci[i][j]);
                    acci[i][j] = fmaf(a[i].y,  b[j].x, acci[i][j]);
                }
        }
        __syncthreads();
    }

    float2* Cb = C + offC + (long)blockIdx.y * BM * ldc + blockIdx.x * BN;
    #pragma unroll
    for (int i = 0; i < TM; i++) {
        int m = ty*TM + i;
        #pragma unroll
        for (int j = 0; j < TN; j++) {
            int n = tx*TN + j;
            float cr = accr[i][j] * scale;
            float ci = acci[i][j] * scale;
            if (bias) { float2 bb = bias[blockIdx.x*BN + n]; cr += bb.x; ci += bb.y; }
            if (act)  { float mag = sqrtf(cr*cr + ci*ci); cr = 0.5f*(cr + mag); ci = 0.5f*ci; }
            Cb[(long)m * ldc + n] = make_float2(cr, ci);
        }
    }
}

// ---------------- softmax over key axis, real & imag independently ----------------
// one warp per row of 512 complex scores
__global__ __launch_bounds__(256)
void softmax_kernel(float2* __restrict__ Sc)
{
    int row  = blockIdx.x * 8 + (threadIdx.x >> 5);
    int lane = threadIdx.x & 31;
    float2* r = Sc + (long)row * SS;

    float2 v[16];
    float mx = -1e30f, my = -1e30f;
    #pragma unroll
    for (int i = 0; i < 16; i++) {
        v[i] = r[lane + 32*i];
        mx = fmaxf(mx, v[i].x); my = fmaxf(my, v[i].y);
    }
    #pragma unroll
    for (int o = 16; o > 0; o >>= 1) {
        mx = fmaxf(mx, __shfl_xor_sync(0xffffffffu, mx, o));
        my = fmaxf(my, __shfl_xor_sync(0xffffffffu, my, o));
    }
    float sx = 0.f, sy = 0.f;
    #pragma unroll
    for (int i = 0; i < 16; i++) {
        v[i].x = __expf(v[i].x - mx);
        v[i].y = __expf(v[i].y - my);
        sx += v[i].x; sy += v[i].y;
    }
    #pragma unroll
    for (int o = 16; o > 0; o >>= 1) {
        sx += __shfl_xor_sync(0xffffffffu, sx, o);
        sy += __shfl_xor_sync(0xffffffffu, sy, o);
    }
    float ix = 1.f / sx, iy = 1.f / sy;
    #pragma unroll
    for (int i = 0; i < 16; i++)
        r[lane + 32*i] = make_float2(v[i].x * ix, v[i].y * iy);
}

// ---------------- block reduction of 4 values (256 threads) ----------------
__device__ __forceinline__
void reduce4(float& a, float& b, float& c, float& d, float* sh)
{
    #pragma unroll
    for (int o = 16; o > 0; o >>= 1) {
        a += __shfl_xor_sync(0xffffffffu, a, o);
        b += __shfl_xor_sync(0xffffffffu, b, o);
        c += __shfl_xor_sync(0xffffffffu, c, o);
        d += __shfl_xor_sync(0xffffffffu, d, o);
    }
    int w = threadIdx.x >> 5;
    __syncthreads();
    if ((threadIdx.x & 31) == 0) {
        sh[w] = a; sh[8+w] = b; sh[16+w] = c; sh[24+w] = d;
    }
    __syncthreads();
    float ra = 0.f, rb = 0.f, rc = 0.f, rd = 0.f;
    #pragma unroll
    for (int i = 0; i < 8; i++) { ra += sh[i]; rb += sh[8+i]; rc += sh[16+i]; rd += sh[24+i]; }
    a = ra; b = rb; c = rc; d = rd;
}

// ---------------- fused double layernorm after attention ----------------
// t = LN0(O + query); X2 = LN1(x + t). real & imag normalized independently.
__global__ __launch_bounds__(256)
void ln_attn_kernel(const float2* __restrict__ O, const float2* __restrict__ query,
                    const float2* __restrict__ x,
                    const float* __restrict__ ln_g, const float* __restrict__ ln_b,
                    float2* __restrict__ X2)
{
    __shared__ float sh[32];
    const long base = (long)blockIdx.x * DDIM;
    const float inv = 1.f / DDIM;

    float2 v[4];
    float sr = 0.f, sqr = 0.f, si = 0.f, sqi = 0.f;
    #pragma unroll
    for (int i = 0; i < 4; i++) {
        int d = threadIdx.x + i*256;
        float2 o = O[base + d], q = query[base + d];
        v[i] = make_float2(o.x + q.x, o.y + q.y);
        sr += v[i].x; sqr += v[i].x * v[i].x;
        si += v[i].y; sqi += v[i].y * v[i].y;
    }
    reduce4(sr, sqr, si, sqi, sh);
    float mr = sr*inv, mi = si*inv;
    float rr = rsqrtf(sqr*inv - mr*mr + LN_EPS);
    float ri = rsqrtf(sqi*inv - mi*mi + LN_EPS);

    float2 u[4];
    float s2r = 0.f, q2r = 0.f, s2i = 0.f, q2i = 0.f;
    #pragma unroll
    for (int i = 0; i < 4; i++) {
        int d = threadIdx.x + i*256;
        float tr = (v[i].x - mr)*rr * ln_g[d]          + ln_b[d];
        float ti = (v[i].y - mi)*ri * ln_g[DDIM + d]   + ln_b[DDIM + d];
        float2 xx = x[base + d];
        u[i] = make_float2(xx.x + tr, xx.y + ti);
        s2r += u[i].x; q2r += u[i].x * u[i].x;
        s2i += u[i].y; q2i += u[i].y * u[i].y;
    }
    reduce4(s2r, q2r, s2i, q2i, sh);
    float m2r = s2r*inv, m2i = s2i*inv;
    float r2r = rsqrtf(q2r*inv - m2r*m2r + LN_EPS);
    float r2i = rsqrtf(q2i*inv - m2i*m2i + LN_EPS);

    const float* g1 = ln_g + 2*DDIM;   // stage 1
    const float* b1 = ln_b + 2*DDIM;
    #pragma unroll
    for (int i = 0; i < 4; i++) {
        int d = threadIdx.x + i*256;
        float yr = (u[i].x - m2r)*r2r * g1[d]        + b1[d];
        float yi = (u[i].y - m2i)*r2i * g1[DDIM + d] + b1[DDIM + d];
        X2[base + d] = make_float2(yr, yi);
    }
}

// ---------------- final layernorm: out = LN2(X2 + Mp) ----------------
__global__ __launch_bounds__(256)
void ln_final_kernel(const float2* __restrict__ X2, const float2* __restrict__ Mp,
                     const float* __restrict__ ln_g, const float* __restrict__ ln_b,
                     float2* __restrict__ out)
{
    __shared__ float sh[32];
    const long base = (long)blockIdx.x * DDIM;
    const float inv = 1.f / DDIM;

    float2 v[4];
    float sr = 0.f, sqr = 0.f, si = 0.f, sqi = 0.f;
    #pragma unroll
    for (int i = 0; i < 4; i++) {
        int d = threadIdx.x + i*256;
        float2 a = X2[base + d], m = Mp[base + d];
        v[i] = make_float2(a.x + m.x, a.y + m.y);
        sr += v[i].x; sqr += v[i].x * v[i].x;
        si += v[i].y; sqi += v[i].y * v[i].y;
    }
    reduce4(sr, sqr, si, sqi, sh);
    float mr = sr*inv, mi = si*inv;
    float rr = rsqrtf(sqr*inv - mr*mr + LN_EPS);
    float ri = rsqrtf(sqi*inv - mi*mi + LN_EPS);

    const float* g2 = ln_g + 4*DDIM;   // stage 2
    const float* b2 = ln_b + 4*DDIM;
    #pragma unroll
    for (int i = 0; i < 4; i++) {
        int d = threadIdx.x + i*256;
        float yr = (v[i].x - mr)*rr * g2[d]        + b2[d];
        float yi = (v[i].y - mi)*ri * g2[DDIM + d] + b2[DDIM + d];
        out[base + d] = make_float2(yr, yi);
    }
}

// ---------------- host launch ----------------
extern "C" void kernel_launch(void* const* d_in, const int* in_sizes, int n_in,
                              void* d_out, int out_size)
{
    const float2* x     = (const float2*)d_in[0];
    const float2* query = (const float2*)d_in[1];
    const float2* wq    = (const float2*)d_in[2];
    const float2* bq    = (const float2*)d_in[3];
    const float2* wk    = (const float2*)d_in[4];
    const float2* bk    = (const float2*)d_in[5];
    const float2* wv    = (const float2*)d_in[6];
    const float2* bv    = (const float2*)d_in[7];
    const float2* wfc   = (const float2*)d_in[8];
    const float2* bfc   = (const float2*)d_in[9];
    const float2* wpr   = (const float2*)d_in[10];
    const float2* bpr   = (const float2*)d_in[11];
    const float*  lng   = (const float*)d_in[12];
    const float*  lnb   = (const float*)d_in[13];

    float2 *Q, *K, *V, *O, *X2, *Mp, *Hm, *Sc;
    cudaGetSymbolAddress((void**)&Q,  g_Q);
    cudaGetSymbolAddress((void**)&K,  g_K);
    cudaGetSymbolAddress((void**)&V,  g_V);
    cudaGetSymbolAddress((void**)&O,  g_O);
    cudaGetSymbolAddress((void**)&X2, g_X2);
    cudaGetSymbolAddress((void**)&Mp, g_Mp);
    cudaGetSymbolAddress((void**)&Hm, g_Hm);
    cudaGetSymbolAddress((void**)&Sc, g_Sc);

    const dim3 blk(NTHR);
    const float rscale = 0.125f;  // 1/sqrt(64)

    // QKV projections: [4096 x 1024] = in @ W^T + b
    {
        dim3 grd(DDIM/BN, MROWS/BM, 1);
        cgemm<true><<<grd, blk>>>(query, DDIM, wq, DDIM, Q, DDIM, DDIM,
                                  0,0,0,0,0,0, 1, bq, 1.f, 0);
        cgemm<true><<<grd, blk>>>(x,     DDIM, wk, DDIM, K, DDIM, DDIM,
                                  0,0,0,0,0,0, 1, bk, 1.f, 0);
        cgemm<true><<<grd, blk>>>(x,     DDIM, wv, DDIM, V, DDIM, DDIM,
                                  0,0,0,0,0,0, 1, bv, 1.f, 0);
    }

    // Scores: S[z, q, k] = scale * Q_z @ K_z^T   (z = b*NH + h)
    {
        dim3 grd(SS/BN, SS/BM, BB*NHEADS);
        cgemm<true><<<grd, blk>>>(Q, DDIM, K, DDIM, Sc, SS, DHEAD,
                                  (long)SS*DDIM, DHEAD,
                                  (long)SS*DDIM, DHEAD,
                                  (long)NHEADS*SS*SS, (long)SS*SS,
                                  NHEADS, (const float2*)nullptr, rscale, 0);
    }

    // Softmax over keys (real & imag independently)
    softmax_kernel<<<(BB*NHEADS*SS)/8, 256>>>(Sc);

    // O = A @ V   (NN form)
    {
        dim3 grd(DHEAD/BN, SS/BM, BB*NHEADS);
        cgemm<false><<<grd, blk>>>(Sc, SS, V, DDIM, O, DDIM, SS,
                                   (long)NHEADS*SS*SS, (long)SS*SS,
                                   (long)SS*DDIM, DHEAD,
                                   (long)SS*DDIM, DHEAD,
                                   NHEADS, (const float2*)nullptr, 1.f, 0);
    }

    // X2 = LN1(x + LN0(O + query))
    ln_attn_kernel<<<MROWS, 256>>>(O, query, x, lng, lnb, X2);

    // fc: Hm = modReLU( X2 @ Wfc^T + bfc )   [4096 x 4096]
    {
        dim3 grd(HDIM/BN, MROWS/BM, 1);
        cgemm<true><<<grd, blk>>>(X2, DDIM, wfc, DDIM, Hm, HDIM, DDIM,
                                  0,0,0,0,0,0, 1, bfc, 1.f, 1);
    }

    // proj: Mp = Hm @ Wproj^T + bproj   [4096 x 1024], K = 4096
    {
        dim3 grd(DDIM/BN, MROWS/BM, 1);
        cgemm<true><<<grd, blk>>>(Hm, HDIM, wpr, HDIM, Mp, DDIM, HDIM,
                                  0,0,0,0,0,0, 1, bpr, 1.f, 0);
    }

    // out = LN2(X2 + Mp)
    ln_final_kernel<<<MROWS, 256>>>(X2, Mp, lng, lnb, (float2*)d_out);
}